// round 8
// baseline (speedup 1.0000x reference)
#include <cuda_runtime.h>
#include <cuda_fp16.h>
#include <cstdint>

#define B_TOK 8192
#define L_DIM 1024
#define D_DIM 2048
#define NE 8

#define BM 128
#define BN 256
#define BKH 64                        // fp16 k per chunk (128B rows)
#define NCH (D_DIM / BKH)             // 32
#define STAGES 4
#define A_BYTES (BM * 128)            // 16384
#define B_BYTES (BN * 128)            // 32768
#define STG_BYTES (A_BYTES + B_BYTES) // 49152
#define DYN_SMEM (STAGES * STG_BYTES) // 196608
#define GATE_SMEM (NE * D_DIM * 4)    // 65536

#define MAX_TILES 72
#define A_TILE_HALVES (BM * D_DIM)            // 262144 halves per tile
#define A_CHUNK_HALVES (BM * BKH)             // 8192 halves = 16KB
#define B_CHUNK_HALVES (BN * BKH)             // 16384 halves = 32KB

// ---------------- scratch (allocation-free rule: __device__ globals) ----------------
__device__ int g_expert[B_TOK];
__device__ int g_counts[NE];
__device__ int g_offsets[NE + 1];
__device__ int g_sorted[B_TOK];
__device__ int g_tilebase[NE];
__device__ int g_tile_e[MAX_TILES];
__device__ int g_tile_m0[MAX_TILES];
__device__ int g_ntiles;
__device__ __half We_h[(size_t)NE * D_DIM * D_DIM];        // 64 MB, chunk-major swizzled
__device__ __half inp_h[(size_t)MAX_TILES * A_TILE_HALVES]; // ~37.7 MB, tile/chunk-major swizzled

// ---------------- helpers ----------------
__device__ __forceinline__ uint32_t smem_u32(const void* p) {
    uint32_t a;
    asm("{ .reg .u64 t; cvta.to.shared.u64 t, %1; cvt.u32.u64 %0, t; }" : "=r"(a) : "l"(p));
    return a;
}
__device__ __forceinline__ void ldsm4(uint32_t* r, uint32_t addr) {
    asm volatile("ldmatrix.sync.aligned.m8n8.x4.shared.b16 {%0,%1,%2,%3}, [%4];"
                 : "=r"(r[0]), "=r"(r[1]), "=r"(r[2]), "=r"(r[3]) : "r"(addr));
}
// fp16-accumulator MMA: d/c are 2 regs (4 halves): reg0 = row lrow cols {2lc,2lc+1}, reg1 = row lrow+8
__device__ __forceinline__ void mma_f16acc(uint32_t* d, const uint32_t* a, const uint32_t* b) {
    asm volatile("mma.sync.aligned.m16n8k16.row.col.f16.f16.f16.f16 "
                 "{%0,%1}, {%2,%3,%4,%5}, {%6,%7}, {%0,%1};"
                 : "+r"(d[0]), "+r"(d[1])
                 : "r"(a[0]), "r"(a[1]), "r"(a[2]), "r"(a[3]), "r"(b[0]), "r"(b[1]));
}
#define MBAR_INIT(addr, count) \
    asm volatile("mbarrier.init.shared.b64 [%0], %1;" :: "r"(addr), "r"((uint32_t)(count)) : "memory")
#define MBAR_EXPECT_TX(addr, bytes) \
    asm volatile("mbarrier.arrive.expect_tx.shared.b64 _, [%0], %1;" :: "r"(addr), "r"((uint32_t)(bytes)) : "memory")
#define MBAR_WAIT(addr, parity) do {                                                \
    uint32_t _m = (addr); uint32_t _p = (parity); uint32_t _done;                   \
    asm volatile("{\n\t.reg .pred p;\n\t"                                           \
        "mbarrier.try_wait.parity.acquire.cta.shared::cta.b64 p, [%1], %2;\n\t"     \
        "selp.b32 %0, 1, 0, p;\n\t}" : "=r"(_done) : "r"(_m), "r"(_p) : "memory");  \
    if (!_done) {                                                                   \
        asm volatile("{\n\t.reg .pred P1;\n\t"                                      \
            "WL_%=:\n\t"                                                            \
            "mbarrier.try_wait.parity.acquire.cta.shared::cta.b64 P1, [%0], %1, 0x989680;\n\t" \
            "@P1 bra.uni WD_%=;\n\t"                                                \
            "bra.uni WL_%=;\n\t"                                                    \
            "WD_%=:\n\t}" :: "r"(_m), "r"(_p) : "memory");                          \
    }                                                                               \
} while (0)
__device__ __forceinline__ void bulk_g2s(uint32_t dst, const void* src, uint32_t bytes, uint32_t mbar) {
    asm volatile("cp.async.bulk.shared::cluster.global.mbarrier::complete_tx::bytes [%0], [%1], %2, [%3];"
                 :: "r"(dst), "l"(src), "r"(bytes), "r"(mbar) : "memory");
}

// ---------------- gating ----------------
__global__ void gate_kernel(const float* __restrict__ x, const float* __restrict__ y,
                            const float* __restrict__ gW, const float* __restrict__ gb) {
    extern __shared__ float sgW[];
    int tid = threadIdx.x;
    for (int i = tid; i < NE * D_DIM / 4; i += 256)
        ((float4*)sgW)[i] = ((const float4*)gW)[i];
    __syncthreads();

    int wid = tid >> 5, lane = tid & 31;
#pragma unroll
    for (int t = 0; t < 4; t++) {
        int tok = blockIdx.x * 32 + wid * 4 + t;
        const float4* xr = (const float4*)(x + (size_t)tok * L_DIM);
        const float4* yr = (const float4*)(y + (size_t)tok * L_DIM);
        float acc[NE];
#pragma unroll
        for (int e = 0; e < NE; e++) acc[e] = 0.f;
#pragma unroll
        for (int it = 0; it < 8; it++) {
            float4 v = xr[it * 32 + lane];
            int kb = (it * 32 + lane) * 4;
#pragma unroll
            for (int e = 0; e < NE; e++) {
                float4 w = *(const float4*)(sgW + e * D_DIM + kb);
                acc[e] += v.x * w.x + v.y * w.y + v.z * w.z + v.w * w.w;
            }
        }
#pragma unroll
        for (int it = 0; it < 8; it++) {
            float4 v = yr[it * 32 + lane];
            int kb = L_DIM + (it * 32 + lane) * 4;
#pragma unroll
            for (int e = 0; e < NE; e++) {
                float4 w = *(const float4*)(sgW + e * D_DIM + kb);
                acc[e] += v.x * w.x + v.y * w.y + v.z * w.z + v.w * w.w;
            }
        }
#pragma unroll
        for (int e = 0; e < NE; e++) {
#pragma unroll
            for (int off = 16; off > 0; off >>= 1)
                acc[e] += __shfl_xor_sync(0xffffffffu, acc[e], off);
        }
        if (lane == 0) {
            int best = 0;
            float bv = acc[0] + gb[0];
#pragma unroll
            for (int e = 1; e < NE; e++) {
                float v = acc[e] + gb[e];
                if (v > bv) { bv = v; best = e; }
            }
            g_expert[tok] = best;
        }
    }
}

// ---------------- fused count + scan + tile-table + rank-scatter (1 block) ----------------
__global__ void sortbuild_kernel() {
    __shared__ int s_cnt[NE];
    __shared__ int s_off[NE];
    int tid = threadIdx.x;            // 1024 threads
    int lane = tid & 31;
    if (tid < NE) s_cnt[tid] = 0;
    __syncthreads();

    int ex[8];
#pragma unroll
    for (int i = 0; i < 8; i++) ex[i] = g_expert[i * 1024 + tid];

    int lc[NE];
#pragma unroll
    for (int e = 0; e < NE; e++) lc[e] = 0;
#pragma unroll
    for (int i = 0; i < 8; i++)
#pragma unroll
        for (int e = 0; e < NE; e++) lc[e] += (ex[i] == e) ? 1 : 0;
#pragma unroll
    for (int e = 0; e < NE; e++) {
#pragma unroll
        for (int off = 16; off > 0; off >>= 1)
            lc[e] += __shfl_xor_sync(0xffffffffu, lc[e], off);
    }
    if (lane == 0) {
#pragma unroll
        for (int e = 0; e < NE; e++) atomicAdd(&s_cnt[e], lc[e]);
    }
    __syncthreads();

    if (tid == 0) {
        int s = 0, tile = 0;
#pragma unroll
        for (int e = 0; e < NE; e++) {
            int c = s_cnt[e];
            g_counts[e] = c;
            g_offsets[e] = s;
            s_off[e] = s;
            g_tilebase[e] = tile;
            int nt = (c + BM - 1) / BM;
            for (int t = 0; t < nt; t++) {
                g_tile_e[tile] = e;
                g_tile_m0[tile] = t * BM;
                tile++;
            }
            s += c;
        }
        g_offsets[NE] = s;
        g_ntiles = tile;
    }
    __syncthreads();

#pragma unroll
    for (int i = 0; i < 8; i++) {
        int tok = i * 1024 + tid;
        int e = ex[i];
        unsigned peers = __match_any_sync(0xffffffffu, e);
        int leader = __ffs(peers) - 1;
        int lrank = __popc(peers & ((1u << lane) - 1u));
        int base = 0;
        if (lane == leader) base = atomicAdd(&s_off[e], __popc(peers));
        base = __shfl_sync(0xffffffffu, base, leader);
        g_sorted[base + lrank] = tok;
    }
}

// ---------------- conversion to chunk-major swizzled fp16 ----------------
__global__ void conv_we(const float* __restrict__ We) {
    uint32_t flat = blockIdx.x * 256 + threadIdx.x;
    int q   = flat & 7;
    int row = (flat >> 3) & 255;
    int ck  = (flat >> 11) & 31;
    int nb  = (flat >> 16) & 7;
    int e   = flat >> 19;
    const float* src = We + ((((size_t)e * D_DIM) + nb * 256 + row) * D_DIM + ck * BKH + q * 8);
    float4 v0 = *(const float4*)src;
    float4 v1 = *(const float4*)(src + 4);
    __half2 h[4];
    h[0] = __floats2half2_rn(v0.x, v0.y);
    h[1] = __floats2half2_rn(v0.z, v0.w);
    h[2] = __floats2half2_rn(v1.x, v1.y);
    h[3] = __floats2half2_rn(v1.z, v1.w);
    __half* dst = We_h + (((size_t)(e * 8 + nb) * 32 + ck) * B_CHUNK_HALVES
                          + row * 64 + ((q ^ (row & 7)) << 3));
    *(uint4*)dst = *(uint4*)h;
}

__global__ void conv_inp(const float* __restrict__ x, const float* __restrict__ y) {
    int tile = blockIdx.x >> 7;
    if (tile >= g_ntiles) return;
    uint32_t fl = (blockIdx.x & 127) * 256 + threadIdx.x;   // 0..32767
    int q   = fl & 7;
    int row = (fl >> 3) & 127;
    int ck  = fl >> 10;
    int e = g_tile_e[tile];
    int m = g_tile_m0[tile] + row;
    __half2 h[4];
    if (m < g_counts[e]) {
        int tok = g_sorted[g_offsets[e] + m];
        int col = ck * BKH + q * 8;
        const float* src = (col < L_DIM) ? (x + (size_t)tok * L_DIM + col)
                                         : (y + (size_t)tok * L_DIM + (col - L_DIM));
        float4 v0 = *(const float4*)src;
        float4 v1 = *(const float4*)(src + 4);
        h[0] = __floats2half2_rn(v0.x, v0.y);
        h[1] = __floats2half2_rn(v0.z, v0.w);
        h[2] = __floats2half2_rn(v1.x, v1.y);
        h[3] = __floats2half2_rn(v1.z, v1.w);
    } else {
        h[0] = h[1] = h[2] = h[3] = __half2half2(__float2half(0.f));
    }
    __half* dst = inp_h + ((size_t)tile * A_TILE_HALVES + (size_t)ck * A_CHUNK_HALVES
                           + row * 64 + ((q ^ (row & 7)) << 3));
    *(uint4*)dst = *(uint4*)h;
}

// ---------------- grouped fp16 GEMM: fp16 acc per chunk, fp32 promotion ----------------
__global__ __launch_bounds__(512, 1)
void moe_gemm_h(const float* __restrict__ be, float* __restrict__ out) {
    int e = blockIdx.z;
    int cnt = g_counts[e];
    int m0 = blockIdx.y * BM;
    if (m0 >= cnt) return;
    int n0 = blockIdx.x * BN;
    const int* toks = g_sorted + g_offsets[e];
    int tile = g_tilebase[e] + blockIdx.y;

    const __half* asrc = inp_h + (size_t)tile * A_TILE_HALVES;
    const __half* bsrc = We_h + ((size_t)(e * 8 + blockIdx.x) * 32) * B_CHUNK_HALVES;

    extern __shared__ char sm[];
    uint32_t sbase = smem_u32(sm);
    __shared__ __align__(8) uint64_t s_mbar[STAGES];
    uint32_t mb[STAGES];
#pragma unroll
    for (int s = 0; s < STAGES; s++) mb[s] = smem_u32(&s_mbar[s]);

    int tid = threadIdx.x, wid = tid >> 5, lane = tid & 31;
    int wm = wid & 3, wn = wid >> 2;          // 4x4 warp grid; warp tile 32(m) x 64(n)
    int lrow = lane >> 2, lc = lane & 3;
    int sw = lane & 7;
    uint32_t aRowBase = (uint32_t)(wm * 32 + ((lane >> 3) & 1) * 8 + sw);
    uint32_t kpa = (uint32_t)(lane >> 4);
    uint32_t nRowBase = (uint32_t)(wn * 64 + (lane >> 4) * 8 + sw);
    uint32_t kpb = (uint32_t)((lane >> 3) & 1);

    if (tid == 0) {
#pragma unroll
        for (int s = 0; s < STAGES; s++) MBAR_INIT(mb[s], 1);
    }
    __syncthreads();

    if (tid == 0) {
#pragma unroll
        for (int s = 0; s < STAGES - 1; s++) {
            uint32_t dst = sbase + s * STG_BYTES;
            MBAR_EXPECT_TX(mb[s], STG_BYTES);
            bulk_g2s(dst, asrc + (size_t)s * A_CHUNK_HALVES, A_BYTES, mb[s]);
            bulk_g2s(dst + A_BYTES, bsrc + (size_t)s * B_CHUNK_HALVES, B_BYTES, mb[s]);
        }
    }

    float acc[2][8][4];
#pragma unroll
    for (int i = 0; i < 2; i++)
#pragma unroll
        for (int j = 0; j < 8; j++)
#pragma unroll
            for (int q = 0; q < 4; q++) acc[i][j][q] = 0.f;

    for (int i = 0; i < NCH; i++) {
        int buf = i & (STAGES - 1);
        if (tid == 0 && i + STAGES - 1 < NCH) {
            int nb = (i + STAGES - 1) & (STAGES - 1);
            uint32_t dst = sbase + nb * STG_BYTES;
            MBAR_EXPECT_TX(mb[nb], STG_BYTES);
            bulk_g2s(dst, asrc + (size_t)(i + STAGES - 1) * A_CHUNK_HALVES, A_BYTES, mb[nb]);
            bulk_g2s(dst + A_BYTES, bsrc + (size_t)(i + STAGES - 1) * B_CHUNK_HALVES, B_BYTES, mb[nb]);
        }
        MBAR_WAIT(mb[buf], (uint32_t)((i >> 2) & 1));

        uint32_t sA = sbase + buf * STG_BYTES;
        uint32_t sB = sA + A_BYTES;

        // fp16 accumulators for this chunk (K=64: 4 MMA roundings per output)
        uint32_t accH[2][8][2];
#pragma unroll
        for (int ii = 0; ii < 2; ii++)
#pragma unroll
            for (int j = 0; j < 8; j++)
                accH[ii][j][0] = accH[ii][j][1] = 0u;

#pragma unroll
        for (int ks = 0; ks < 4; ks++) {
            uint32_t a[2][4], b[4][4];
            uint32_t chA = (uint32_t)(((ks * 2 + kpa) ^ sw) << 4);
            uint32_t chB = (uint32_t)(((ks * 2 + kpb) ^ sw) << 4);
#pragma unroll
            for (int ii = 0; ii < 2; ii++)
                ldsm4(a[ii], sA + (aRowBase + ii * 16) * 128u + chA);
#pragma unroll
            for (int jp = 0; jp < 4; jp++)
                ldsm4(b[jp], sB + (nRowBase + jp * 16) * 128u + chB);
#pragma unroll
            for (int ii = 0; ii < 2; ii++)
#pragma unroll
                for (int jp = 0; jp < 4; jp++) {
                    mma_f16acc(accH[ii][jp * 2 + 0], a[ii], &b[jp][0]);
                    mma_f16acc(accH[ii][jp * 2 + 1], a[ii], &b[jp][2]);
                }
        }
        // promote chunk partials to fp32
#pragma unroll
        for (int ii = 0; ii < 2; ii++)
#pragma unroll
            for (int j = 0; j < 8; j++) {
                float2 lo = __half22float2(*(const __half2*)&accH[ii][j][0]);
                float2 hi = __half22float2(*(const __half2*)&accH[ii][j][1]);
                acc[ii][j][0] += lo.x;
                acc[ii][j][1] += lo.y;
                acc[ii][j][2] += hi.x;
                acc[ii][j][3] += hi.y;
            }
        __syncthreads();
    }

    // ---- epilogue: bias + scatter to original token rows ----
    const float* brow_g = be + (size_t)e * D_DIM + n0 + wn * 64 + lc * 2;
    float2 bias[8];
#pragma unroll
    for (int j = 0; j < 8; j++) bias[j] = *(const float2*)(brow_g + j * 8);

#pragma unroll
    for (int ii = 0; ii < 2; ii++) {
#pragma unroll
        for (int h = 0; h < 2; h++) {
            int m = m0 + wm * 32 + ii * 16 + h * 8 + lrow;
            if (m < cnt) {
                int tok = toks[m];
                float* orow = out + (size_t)tok * D_DIM + n0 + wn * 64 + lc * 2;
#pragma unroll
                for (int j = 0; j < 8; j++) {
                    float2 v;
                    v.x = acc[ii][j][h * 2 + 0] + bias[j].x;
                    v.y = acc[ii][j][h * 2 + 1] + bias[j].y;
                    *(float2*)(orow + j * 8) = v;
                }
            }
        }
    }
}

extern "C" void kernel_launch(void* const* d_in, const int* in_sizes, int n_in,
                              void* d_out, int out_size) {
    const float* x  = (const float*)d_in[0];
    const float* y  = (const float*)d_in[1];
    const float* We = (const float*)d_in[2];
    const float* be = (const float*)d_in[3];
    const float* gW = (const float*)d_in[4];
    const float* gb = (const float*)d_in[5];
    float* out = (float*)d_out;

    static cudaStream_t s2 = nullptr;
    static cudaEvent_t evFork = nullptr, evWe = nullptr;
    if (!s2) {
        cudaFuncSetAttribute(moe_gemm_h, cudaFuncAttributeMaxDynamicSharedMemorySize, DYN_SMEM);
        cudaFuncSetAttribute(gate_kernel, cudaFuncAttributeMaxDynamicSharedMemorySize, GATE_SMEM);
        cudaStreamCreateWithFlags(&s2, cudaStreamNonBlocking);
        cudaEventCreateWithFlags(&evFork, cudaEventDisableTiming);
        cudaEventCreateWithFlags(&evWe, cudaEventDisableTiming);
    }

    // fork: conv_we runs on s2 concurrently with the gating chain
    cudaEventRecord(evFork, 0);
    cudaStreamWaitEvent(s2, evFork, 0);
    conv_we<<<(NE * D_DIM * D_DIM) / (256 * 8), 256, 0, s2>>>(We);
    cudaEventRecord(evWe, s2);

    gate_kernel<<<B_TOK / 32, 256, GATE_SMEM>>>(x, y, gW, gb);
    sortbuild_kernel<<<1, 1024>>>();
    conv_inp<<<MAX_TILES * 128, 256>>>(x, y);

    // join: GEMM needs We_h
    cudaStreamWaitEvent(0, evWe, 0);

    dim3 grid(D_DIM / BN, (B_TOK + BM - 1) / BM, NE);  // 8 x 64 x 8; empty m-tiles exit early
    moe_gemm_h<<<grid, 512, DYN_SMEM>>>(be, out);
}

// round 9
// speedup vs baseline: 1.1212x; 1.1212x over previous
#include <cuda_runtime.h>
#include <cuda_fp16.h>
#include <cstdint>

#define B_TOK 8192
#define L_DIM 1024
#define D_DIM 2048
#define NE 8

#define BM 128
#define BN 64
#define BKH 64                        // fp16 k per chunk (128B rows)
#define NCH (D_DIM / BKH)             // 32
#define STAGES 4
#define A_BYTES (BM * 128)            // 16384
#define B_BYTES (BN * 128)            // 8192
#define STG_BYTES (A_BYTES + B_BYTES) // 24576
#define DYN_SMEM (STAGES * STG_BYTES) // 98304
#define GATE_SMEM (NE * D_DIM * 4)    // 65536

#define MAX_TILES 72
#define A_TILE_HALVES (BM * D_DIM)            // 262144 halves per tile
#define A_CHUNK_HALVES (BM * BKH)             // 8192 halves = 16KB
#define B_CHUNK_HALVES (BN * BKH)             // 4096 halves = 8KB

// ---------------- scratch (allocation-free rule: __device__ globals) ----------------
__device__ int g_expert[B_TOK];
__device__ int g_counts[NE];
__device__ int g_offsets[NE + 1];
__device__ int g_sorted[B_TOK];
__device__ int g_tilebase[NE];
__device__ int g_tile_e[MAX_TILES];
__device__ int g_tile_m0[MAX_TILES];
__device__ int g_ntiles;
__device__ __half We_h[(size_t)NE * D_DIM * D_DIM];        // 64 MB, chunk-major swizzled
__device__ __half inp_h[(size_t)MAX_TILES * A_TILE_HALVES]; // ~37.7 MB, tile/chunk-major swizzled

// ---------------- helpers ----------------
__device__ __forceinline__ uint32_t smem_u32(const void* p) {
    uint32_t a;
    asm("{ .reg .u64 t; cvta.to.shared.u64 t, %1; cvt.u32.u64 %0, t; }" : "=r"(a) : "l"(p));
    return a;
}
__device__ __forceinline__ void ldsm4(uint32_t* r, uint32_t addr) {
    asm volatile("ldmatrix.sync.aligned.m8n8.x4.shared.b16 {%0,%1,%2,%3}, [%4];"
                 : "=r"(r[0]), "=r"(r[1]), "=r"(r[2]), "=r"(r[3]) : "r"(addr));
}
__device__ __forceinline__ void mma_f16(float* d, const uint32_t* a, const uint32_t* b) {
    asm volatile("mma.sync.aligned.m16n8k16.row.col.f32.f16.f16.f32 "
                 "{%0,%1,%2,%3}, {%4,%5,%6,%7}, {%8,%9}, {%0,%1,%2,%3};"
                 : "+f"(d[0]), "+f"(d[1]), "+f"(d[2]), "+f"(d[3])
                 : "r"(a[0]), "r"(a[1]), "r"(a[2]), "r"(a[3]), "r"(b[0]), "r"(b[1]));
}
#define MBAR_INIT(addr, count) \
    asm volatile("mbarrier.init.shared.b64 [%0], %1;" :: "r"(addr), "r"((uint32_t)(count)) : "memory")
#define MBAR_EXPECT_TX(addr, bytes) \
    asm volatile("mbarrier.arrive.expect_tx.shared.b64 _, [%0], %1;" :: "r"(addr), "r"((uint32_t)(bytes)) : "memory")
#define MBAR_WAIT(addr, parity) do {                                                \
    uint32_t _m = (addr); uint32_t _p = (parity); uint32_t _done;                   \
    asm volatile("{\n\t.reg .pred p;\n\t"                                           \
        "mbarrier.try_wait.parity.acquire.cta.shared::cta.b64 p, [%1], %2;\n\t"     \
        "selp.b32 %0, 1, 0, p;\n\t}" : "=r"(_done) : "r"(_m), "r"(_p) : "memory");  \
    if (!_done) {                                                                   \
        asm volatile("{\n\t.reg .pred P1;\n\t"                                      \
            "WL_%=:\n\t"                                                            \
            "mbarrier.try_wait.parity.acquire.cta.shared::cta.b64 P1, [%0], %1, 0x989680;\n\t" \
            "@P1 bra.uni WD_%=;\n\t"                                                \
            "bra.uni WL_%=;\n\t"                                                    \
            "WD_%=:\n\t}" :: "r"(_m), "r"(_p) : "memory");                          \
    }                                                                               \
} while (0)
__device__ __forceinline__ void bulk_g2s(uint32_t dst, const void* src, uint32_t bytes, uint32_t mbar) {
    asm volatile("cp.async.bulk.shared::cluster.global.mbarrier::complete_tx::bytes [%0], [%1], %2, [%3];"
                 :: "r"(dst), "l"(src), "r"(bytes), "r"(mbar) : "memory");
}

// ---------------- gating ----------------
__global__ void gate_kernel(const float* __restrict__ x, const float* __restrict__ y,
                            const float* __restrict__ gW, const float* __restrict__ gb) {
    extern __shared__ float sgW[];
    int tid = threadIdx.x;
    for (int i = tid; i < NE * D_DIM / 4; i += 256)
        ((float4*)sgW)[i] = ((const float4*)gW)[i];
    __syncthreads();

    int wid = tid >> 5, lane = tid & 31;
#pragma unroll
    for (int t = 0; t < 4; t++) {
        int tok = blockIdx.x * 32 + wid * 4 + t;
        const float4* xr = (const float4*)(x + (size_t)tok * L_DIM);
        const float4* yr = (const float4*)(y + (size_t)tok * L_DIM);
        float acc[NE];
#pragma unroll
        for (int e = 0; e < NE; e++) acc[e] = 0.f;
#pragma unroll
        for (int it = 0; it < 8; it++) {
            float4 v = xr[it * 32 + lane];
            int kb = (it * 32 + lane) * 4;
#pragma unroll
            for (int e = 0; e < NE; e++) {
                float4 w = *(const float4*)(sgW + e * D_DIM + kb);
                acc[e] += v.x * w.x + v.y * w.y + v.z * w.z + v.w * w.w;
            }
        }
#pragma unroll
        for (int it = 0; it < 8; it++) {
            float4 v = yr[it * 32 + lane];
            int kb = L_DIM + (it * 32 + lane) * 4;
#pragma unroll
            for (int e = 0; e < NE; e++) {
                float4 w = *(const float4*)(sgW + e * D_DIM + kb);
                acc[e] += v.x * w.x + v.y * w.y + v.z * w.z + v.w * w.w;
            }
        }
#pragma unroll
        for (int e = 0; e < NE; e++) {
#pragma unroll
            for (int off = 16; off > 0; off >>= 1)
                acc[e] += __shfl_xor_sync(0xffffffffu, acc[e], off);
        }
        if (lane == 0) {
            int best = 0;
            float bv = acc[0] + gb[0];
#pragma unroll
            for (int e = 1; e < NE; e++) {
                float v = acc[e] + gb[e];
                if (v > bv) { bv = v; best = e; }
            }
            g_expert[tok] = best;
        }
    }
}

// ---------------- fused count + scan + tile-table + rank-scatter (1 block) ----------------
__global__ void sortbuild_kernel() {
    __shared__ int s_cnt[NE];
    __shared__ int s_off[NE];
    int tid = threadIdx.x;            // 1024 threads
    int lane = tid & 31;
    if (tid < NE) s_cnt[tid] = 0;
    __syncthreads();

    int ex[8];
#pragma unroll
    for (int i = 0; i < 8; i++) ex[i] = g_expert[i * 1024 + tid];

    int lc[NE];
#pragma unroll
    for (int e = 0; e < NE; e++) lc[e] = 0;
#pragma unroll
    for (int i = 0; i < 8; i++)
#pragma unroll
        for (int e = 0; e < NE; e++) lc[e] += (ex[i] == e) ? 1 : 0;
#pragma unroll
    for (int e = 0; e < NE; e++) {
#pragma unroll
        for (int off = 16; off > 0; off >>= 1)
            lc[e] += __shfl_xor_sync(0xffffffffu, lc[e], off);
    }
    if (lane == 0) {
#pragma unroll
        for (int e = 0; e < NE; e++) atomicAdd(&s_cnt[e], lc[e]);
    }
    __syncthreads();

    if (tid == 0) {
        int s = 0, tile = 0;
#pragma unroll
        for (int e = 0; e < NE; e++) {
            int c = s_cnt[e];
            g_counts[e] = c;
            g_offsets[e] = s;
            s_off[e] = s;
            g_tilebase[e] = tile;
            int nt = (c + BM - 1) / BM;
            for (int t = 0; t < nt; t++) {
                g_tile_e[tile] = e;
                g_tile_m0[tile] = t * BM;
                tile++;
            }
            s += c;
        }
        g_offsets[NE] = s;
        g_ntiles = tile;
    }
    __syncthreads();

#pragma unroll
    for (int i = 0; i < 8; i++) {
        int tok = i * 1024 + tid;
        int e = ex[i];
        unsigned peers = __match_any_sync(0xffffffffu, e);
        int leader = __ffs(peers) - 1;
        int lrank = __popc(peers & ((1u << lane) - 1u));
        int base = 0;
        if (lane == leader) base = atomicAdd(&s_off[e], __popc(peers));
        base = __shfl_sync(0xffffffffu, base, leader);
        g_sorted[base + lrank] = tok;
    }
}

// ---------------- conversion to chunk-major swizzled fp16 ----------------
// We_h layout: [e][nb(32)][ck(32)][row(64)][64 halves], 16B chunk q stored at (q ^ (row&7)).
__global__ void conv_we(const float* __restrict__ We) {
    uint32_t flat = blockIdx.x * 256 + threadIdx.x;
    int q   = flat & 7;
    int row = (flat >> 3) & 63;
    int ck  = (flat >> 9) & 31;
    int nb  = (flat >> 14) & 31;
    int e   = flat >> 19;
    const float* src = We + ((((size_t)e * D_DIM) + nb * 64 + row) * D_DIM + ck * BKH + q * 8);
    float4 v0 = *(const float4*)src;
    float4 v1 = *(const float4*)(src + 4);
    __half2 h[4];
    h[0] = __floats2half2_rn(v0.x, v0.y);
    h[1] = __floats2half2_rn(v0.z, v0.w);
    h[2] = __floats2half2_rn(v1.x, v1.y);
    h[3] = __floats2half2_rn(v1.z, v1.w);
    __half* dst = We_h + (((size_t)(e * 32 + nb) * 32 + ck) * B_CHUNK_HALVES
                          + row * 64 + ((q ^ (row & 7)) << 3));
    *(uint4*)dst = *(uint4*)h;
}

// inp_h layout: [tile][ck(32)][row(128)][64 halves], swizzled; rows = sorted tokens.
__global__ void conv_inp(const float* __restrict__ x, const float* __restrict__ y) {
    int tile = blockIdx.x >> 7;
    if (tile >= g_ntiles) return;
    uint32_t fl = (blockIdx.x & 127) * 256 + threadIdx.x;   // 0..32767
    int q   = fl & 7;
    int row = (fl >> 3) & 127;
    int ck  = fl >> 10;
    int e = g_tile_e[tile];
    int m = g_tile_m0[tile] + row;
    __half2 h[4];
    if (m < g_counts[e]) {
        int tok = g_sorted[g_offsets[e] + m];
        int col = ck * BKH + q * 8;
        const float* src = (col < L_DIM) ? (x + (size_t)tok * L_DIM + col)
                                         : (y + (size_t)tok * L_DIM + (col - L_DIM));
        float4 v0 = *(const float4*)src;
        float4 v1 = *(const float4*)(src + 4);
        h[0] = __floats2half2_rn(v0.x, v0.y);
        h[1] = __floats2half2_rn(v0.z, v0.w);
        h[2] = __floats2half2_rn(v1.x, v1.y);
        h[3] = __floats2half2_rn(v1.z, v1.w);
    } else {
        h[0] = h[1] = h[2] = h[3] = __half2half2(__float2half(0.f));
    }
    __half* dst = inp_h + ((size_t)tile * A_TILE_HALVES + (size_t)ck * A_CHUNK_HALVES
                           + row * 64 + ((q ^ (row & 7)) << 3));
    *(uint4*)dst = *(uint4*)h;
}

// ---------------- grouped fp16 mma.sync GEMM, 256 threads, tile 128x64 ----------------
__global__ __launch_bounds__(256)
void moe_gemm_h(const float* __restrict__ be, float* __restrict__ out) {
    int tile = blockIdx.y;
    if (tile >= g_ntiles) return;
    int e = g_tile_e[tile];
    int m0 = g_tile_m0[tile];
    int cnt = g_counts[e];
    int nb = blockIdx.x;
    int n0 = nb * BN;
    const int* toks = g_sorted + g_offsets[e];

    const __half* asrc = inp_h + (size_t)tile * A_TILE_HALVES;
    const __half* bsrc = We_h + ((size_t)(e * 32 + nb) * 32) * B_CHUNK_HALVES;

    extern __shared__ char sm[];
    uint32_t sbase = smem_u32(sm);
    __shared__ __align__(8) uint64_t s_mbar[STAGES];
    uint32_t mb[STAGES];
#pragma unroll
    for (int s = 0; s < STAGES; s++) mb[s] = smem_u32(&s_mbar[s]);

    int tid = threadIdx.x, wid = tid >> 5, lane = tid & 31;
    int wm = wid & 3, wn = wid >> 2;          // 4x2 warp grid; warp tile 32(m) x 32(n)
    int lrow = lane >> 2, lc = lane & 3;
    int sw = lane & 7;
    uint32_t aRowBase = (uint32_t)(wm * 32 + ((lane >> 3) & 1) * 8 + sw);
    uint32_t kpa = (uint32_t)(lane >> 4);
    uint32_t nRowBase = (uint32_t)(wn * 32 + (lane >> 4) * 8 + sw);
    uint32_t kpb = (uint32_t)((lane >> 3) & 1);

    if (tid == 0) {
#pragma unroll
        for (int s = 0; s < STAGES; s++) MBAR_INIT(mb[s], 1);
    }
    __syncthreads();

    if (tid == 0) {
#pragma unroll
        for (int s = 0; s < STAGES - 1; s++) {
            uint32_t dst = sbase + s * STG_BYTES;
            MBAR_EXPECT_TX(mb[s], STG_BYTES);
            bulk_g2s(dst, asrc + (size_t)s * A_CHUNK_HALVES, A_BYTES, mb[s]);
            bulk_g2s(dst + A_BYTES, bsrc + (size_t)s * B_CHUNK_HALVES, B_BYTES, mb[s]);
        }
    }

    float acc[2][4][4];
#pragma unroll
    for (int i = 0; i < 2; i++)
#pragma unroll
        for (int j = 0; j < 4; j++)
#pragma unroll
            for (int q = 0; q < 4; q++) acc[i][j][q] = 0.f;

    for (int i = 0; i < NCH; i++) {
        int buf = i & (STAGES - 1);
        if (tid == 0 && i + STAGES - 1 < NCH) {
            int nxt = (i + STAGES - 1) & (STAGES - 1);
            uint32_t dst = sbase + nxt * STG_BYTES;
            MBAR_EXPECT_TX(mb[nxt], STG_BYTES);
            bulk_g2s(dst, asrc + (size_t)(i + STAGES - 1) * A_CHUNK_HALVES, A_BYTES, mb[nxt]);
            bulk_g2s(dst + A_BYTES, bsrc + (size_t)(i + STAGES - 1) * B_CHUNK_HALVES, B_BYTES, mb[nxt]);
        }
        MBAR_WAIT(mb[buf], (uint32_t)((i >> 2) & 1));

        uint32_t sA = sbase + buf * STG_BYTES;
        uint32_t sB = sA + A_BYTES;
#pragma unroll
        for (int ks = 0; ks < 4; ks++) {
            uint32_t a[2][4], b[2][4];
            uint32_t chA = (uint32_t)(((ks * 2 + kpa) ^ sw) << 4);
            uint32_t chB = (uint32_t)(((ks * 2 + kpb) ^ sw) << 4);
#pragma unroll
            for (int ii = 0; ii < 2; ii++)
                ldsm4(a[ii], sA + (aRowBase + ii * 16) * 128u + chA);
#pragma unroll
            for (int jp = 0; jp < 2; jp++)
                ldsm4(b[jp], sB + (nRowBase + jp * 16) * 128u + chB);
#pragma unroll
            for (int ii = 0; ii < 2; ii++)
#pragma unroll
                for (int jp = 0; jp < 2; jp++) {
                    mma_f16(acc[ii][jp * 2 + 0], a[ii], &b[jp][0]);
                    mma_f16(acc[ii][jp * 2 + 1], a[ii], &b[jp][2]);
                }
        }
        __syncthreads();
    }

    // ---- epilogue: bias + scatter to original token rows ----
    const float* brow_g = be + (size_t)e * D_DIM + n0 + wn * 32 + lc * 2;
    float2 bias[4];
#pragma unroll
    for (int j = 0; j < 4; j++) bias[j] = *(const float2*)(brow_g + j * 8);

#pragma unroll
    for (int ii = 0; ii < 2; ii++) {
#pragma unroll
        for (int h = 0; h < 2; h++) {
            int m = m0 + wm * 32 + ii * 16 + h * 8 + lrow;
            if (m < cnt) {
                int tok = toks[m];
                float* orow = out + (size_t)tok * D_DIM + n0 + wn * 32 + lc * 2;
#pragma unroll
                for (int j = 0; j < 4; j++) {
                    float2 v;
                    v.x = acc[ii][j][h * 2 + 0] + bias[j].x;
                    v.y = acc[ii][j][h * 2 + 1] + bias[j].y;
                    *(float2*)(orow + j * 8) = v;
                }
            }
        }
    }
}

extern "C" void kernel_launch(void* const* d_in, const int* in_sizes, int n_in,
                              void* d_out, int out_size) {
    const float* x  = (const float*)d_in[0];
    const float* y  = (const float*)d_in[1];
    const float* We = (const float*)d_in[2];
    const float* be = (const float*)d_in[3];
    const float* gW = (const float*)d_in[4];
    const float* gb = (const float*)d_in[5];
    float* out = (float*)d_out;

    static cudaStream_t s2 = nullptr;
    static cudaEvent_t evFork = nullptr, evWe = nullptr;
    if (!s2) {
        cudaFuncSetAttribute(moe_gemm_h, cudaFuncAttributeMaxDynamicSharedMemorySize, DYN_SMEM);
        cudaFuncSetAttribute(gate_kernel, cudaFuncAttributeMaxDynamicSharedMemorySize, GATE_SMEM);
        cudaStreamCreateWithFlags(&s2, cudaStreamNonBlocking);
        cudaEventCreateWithFlags(&evFork, cudaEventDisableTiming);
        cudaEventCreateWithFlags(&evWe, cudaEventDisableTiming);
    }

    // fork: conv_we runs on s2 concurrently with the gating chain
    cudaEventRecord(evFork, 0);
    cudaStreamWaitEvent(s2, evFork, 0);
    conv_we<<<(NE * D_DIM * D_DIM) / (256 * 8), 256, 0, s2>>>(We);
    cudaEventRecord(evWe, s2);

    gate_kernel<<<B_TOK / 32, 256, GATE_SMEM>>>(x, y, gW, gb);
    sortbuild_kernel<<<1, 1024>>>();
    conv_inp<<<MAX_TILES * 128, 256>>>(x, y);

    // join: GEMM needs We_h
    cudaStreamWaitEvent(0, evWe, 0);

    dim3 grid(D_DIM / BN, MAX_TILES, 1);   // 32 x 72; tiles >= g_ntiles exit early
    moe_gemm_h<<<grid, 256, DYN_SMEM>>>(be, out);
}

// round 10
// speedup vs baseline: 1.1490x; 1.0248x over previous
#include <cuda_runtime.h>
#include <cuda_fp16.h>
#include <cstdint>

#define B_TOK 8192
#define L_DIM 1024
#define D_DIM 2048
#define NE 8

#define BM 64
#define BN 128
#define BKH 64                        // fp16 k per chunk (128B rows)
#define NCH (D_DIM / BKH)             // 32
#define STAGES 4
#define A_BYTES (BM * 128)            // 8192
#define B_BYTES (BN * 128)            // 16384
#define STG_BYTES (A_BYTES + B_BYTES) // 24576
#define DYN_SMEM (STAGES * STG_BYTES) // 98304
#define GATE_SMEM (NE * D_DIM * 4)    // 65536

#define MAX_TILES 136
#define A_TILE_HALVES (BM * D_DIM)            // 131072 halves per tile
#define A_CHUNK_HALVES (BM * BKH)             // 4096 halves = 8KB
#define B_CHUNK_HALVES (BN * BKH)             // 8192 halves = 16KB

// ---------------- scratch (allocation-free rule: __device__ globals) ----------------
__device__ int g_expert[B_TOK];
__device__ int g_counts[NE];
__device__ int g_offsets[NE + 1];
__device__ int g_sorted[B_TOK];
__device__ int g_tilebase[NE];
__device__ int g_tile_e[MAX_TILES];
__device__ int g_tile_m0[MAX_TILES];
__device__ int g_ntiles;
__device__ __half We_h[(size_t)NE * D_DIM * D_DIM];        // 64 MB, chunk-major swizzled
__device__ __half inp_h[(size_t)MAX_TILES * A_TILE_HALVES]; // ~35.7 MB, tile/chunk-major swizzled

// ---------------- helpers ----------------
__device__ __forceinline__ uint32_t smem_u32(const void* p) {
    uint32_t a;
    asm("{ .reg .u64 t; cvta.to.shared.u64 t, %1; cvt.u32.u64 %0, t; }" : "=r"(a) : "l"(p));
    return a;
}
__device__ __forceinline__ void ldsm4(uint32_t* r, uint32_t addr) {
    asm volatile("ldmatrix.sync.aligned.m8n8.x4.shared.b16 {%0,%1,%2,%3}, [%4];"
                 : "=r"(r[0]), "=r"(r[1]), "=r"(r[2]), "=r"(r[3]) : "r"(addr));
}
__device__ __forceinline__ void mma_f16(float* d, const uint32_t* a, const uint32_t* b) {
    asm volatile("mma.sync.aligned.m16n8k16.row.col.f32.f16.f16.f32 "
                 "{%0,%1,%2,%3}, {%4,%5,%6,%7}, {%8,%9}, {%0,%1,%2,%3};"
                 : "+f"(d[0]), "+f"(d[1]), "+f"(d[2]), "+f"(d[3])
                 : "r"(a[0]), "r"(a[1]), "r"(a[2]), "r"(a[3]), "r"(b[0]), "r"(b[1]));
}
#define MBAR_INIT(addr, count) \
    asm volatile("mbarrier.init.shared.b64 [%0], %1;" :: "r"(addr), "r"((uint32_t)(count)) : "memory")
#define MBAR_EXPECT_TX(addr, bytes) \
    asm volatile("mbarrier.arrive.expect_tx.shared.b64 _, [%0], %1;" :: "r"(addr), "r"((uint32_t)(bytes)) : "memory")
#define MBAR_WAIT(addr, parity) do {                                                \
    uint32_t _m = (addr); uint32_t _p = (parity); uint32_t _done;                   \
    asm volatile("{\n\t.reg .pred p;\n\t"                                           \
        "mbarrier.try_wait.parity.acquire.cta.shared::cta.b64 p, [%1], %2;\n\t"     \
        "selp.b32 %0, 1, 0, p;\n\t}" : "=r"(_done) : "r"(_m), "r"(_p) : "memory");  \
    if (!_done) {                                                                   \
        asm volatile("{\n\t.reg .pred P1;\n\t"                                      \
            "WL_%=:\n\t"                                                            \
            "mbarrier.try_wait.parity.acquire.cta.shared::cta.b64 P1, [%0], %1, 0x989680;\n\t" \
            "@P1 bra.uni WD_%=;\n\t"                                                \
            "bra.uni WL_%=;\n\t"                                                    \
            "WD_%=:\n\t}" :: "r"(_m), "r"(_p) : "memory");                          \
    }                                                                               \
} while (0)
__device__ __forceinline__ void bulk_g2s(uint32_t dst, const void* src, uint32_t bytes, uint32_t mbar) {
    asm volatile("cp.async.bulk.shared::cluster.global.mbarrier::complete_tx::bytes [%0], [%1], %2, [%3];"
                 :: "r"(dst), "l"(src), "r"(bytes), "r"(mbar) : "memory");
}

// ---------------- gating ----------------
__global__ void gate_kernel(const float* __restrict__ x, const float* __restrict__ y,
                            const float* __restrict__ gW, const float* __restrict__ gb) {
    extern __shared__ float sgW[];
    int tid = threadIdx.x;
    for (int i = tid; i < NE * D_DIM / 4; i += 256)
        ((float4*)sgW)[i] = ((const float4*)gW)[i];
    __syncthreads();

    int wid = tid >> 5, lane = tid & 31;
#pragma unroll
    for (int t = 0; t < 4; t++) {
        int tok = blockIdx.x * 32 + wid * 4 + t;
        const float4* xr = (const float4*)(x + (size_t)tok * L_DIM);
        const float4* yr = (const float4*)(y + (size_t)tok * L_DIM);
        float acc[NE];
#pragma unroll
        for (int e = 0; e < NE; e++) acc[e] = 0.f;
#pragma unroll
        for (int it = 0; it < 8; it++) {
            float4 v = xr[it * 32 + lane];
            int kb = (it * 32 + lane) * 4;
#pragma unroll
            for (int e = 0; e < NE; e++) {
                float4 w = *(const float4*)(sgW + e * D_DIM + kb);
                acc[e] += v.x * w.x + v.y * w.y + v.z * w.z + v.w * w.w;
            }
        }
#pragma unroll
        for (int it = 0; it < 8; it++) {
            float4 v = yr[it * 32 + lane];
            int kb = L_DIM + (it * 32 + lane) * 4;
#pragma unroll
            for (int e = 0; e < NE; e++) {
                float4 w = *(const float4*)(sgW + e * D_DIM + kb);
                acc[e] += v.x * w.x + v.y * w.y + v.z * w.z + v.w * w.w;
            }
        }
#pragma unroll
        for (int e = 0; e < NE; e++) {
#pragma unroll
            for (int off = 16; off > 0; off >>= 1)
                acc[e] += __shfl_xor_sync(0xffffffffu, acc[e], off);
        }
        if (lane == 0) {
            int best = 0;
            float bv = acc[0] + gb[0];
#pragma unroll
            for (int e = 1; e < NE; e++) {
                float v = acc[e] + gb[e];
                if (v > bv) { bv = v; best = e; }
            }
            g_expert[tok] = best;
        }
    }
}

// ---------------- fused count + scan + tile-table + rank-scatter (1 block) ----------------
__global__ void sortbuild_kernel() {
    __shared__ int s_cnt[NE];
    __shared__ int s_off[NE];
    int tid = threadIdx.x;            // 1024 threads
    int lane = tid & 31;
    if (tid < NE) s_cnt[tid] = 0;
    __syncthreads();

    int ex[8];
#pragma unroll
    for (int i = 0; i < 8; i++) ex[i] = g_expert[i * 1024 + tid];

    int lc[NE];
#pragma unroll
    for (int e = 0; e < NE; e++) lc[e] = 0;
#pragma unroll
    for (int i = 0; i < 8; i++)
#pragma unroll
        for (int e = 0; e < NE; e++) lc[e] += (ex[i] == e) ? 1 : 0;
#pragma unroll
    for (int e = 0; e < NE; e++) {
#pragma unroll
        for (int off = 16; off > 0; off >>= 1)
            lc[e] += __shfl_xor_sync(0xffffffffu, lc[e], off);
    }
    if (lane == 0) {
#pragma unroll
        for (int e = 0; e < NE; e++) atomicAdd(&s_cnt[e], lc[e]);
    }
    __syncthreads();

    if (tid == 0) {
        int s = 0, tile = 0;
#pragma unroll
        for (int e = 0; e < NE; e++) {
            int c = s_cnt[e];
            g_counts[e] = c;
            g_offsets[e] = s;
            s_off[e] = s;
            g_tilebase[e] = tile;
            int nt = (c + BM - 1) / BM;
            for (int t = 0; t < nt; t++) {
                g_tile_e[tile] = e;
                g_tile_m0[tile] = t * BM;
                tile++;
            }
            s += c;
        }
        g_offsets[NE] = s;
        g_ntiles = tile;
    }
    __syncthreads();

#pragma unroll
    for (int i = 0; i < 8; i++) {
        int tok = i * 1024 + tid;
        int e = ex[i];
        unsigned peers = __match_any_sync(0xffffffffu, e);
        int leader = __ffs(peers) - 1;
        int lrank = __popc(peers & ((1u << lane) - 1u));
        int base = 0;
        if (lane == leader) base = atomicAdd(&s_off[e], __popc(peers));
        base = __shfl_sync(0xffffffffu, base, leader);
        g_sorted[base + lrank] = tok;
    }
}

// ---------------- conversion to chunk-major swizzled fp16 ----------------
// We_h layout: [e][nb(16)][ck(32)][row(128)][64 halves], 16B chunk q stored at (q ^ (row&7)).
__global__ void conv_we(const float* __restrict__ We) {
    uint32_t flat = blockIdx.x * 256 + threadIdx.x;
    int q   = flat & 7;
    int row = (flat >> 3) & 127;
    int ck  = (flat >> 10) & 31;
    int nb  = (flat >> 15) & 15;
    int e   = flat >> 19;
    const float* src = We + ((((size_t)e * D_DIM) + nb * 128 + row) * D_DIM + ck * BKH + q * 8);
    float4 v0 = *(const float4*)src;
    float4 v1 = *(const float4*)(src + 4);
    __half2 h[4];
    h[0] = __floats2half2_rn(v0.x, v0.y);
    h[1] = __floats2half2_rn(v0.z, v0.w);
    h[2] = __floats2half2_rn(v1.x, v1.y);
    h[3] = __floats2half2_rn(v1.z, v1.w);
    __half* dst = We_h + (((size_t)(e * 16 + nb) * 32 + ck) * B_CHUNK_HALVES
                          + row * 64 + ((q ^ (row & 7)) << 3));
    *(uint4*)dst = *(uint4*)h;
}

// inp_h layout: [tile][ck(32)][row(64)][64 halves], swizzled; rows = sorted tokens.
__global__ void conv_inp(const float* __restrict__ x, const float* __restrict__ y) {
    int tile = blockIdx.x >> 6;
    if (tile >= g_ntiles) return;
    uint32_t fl = (blockIdx.x & 63) * 256 + threadIdx.x;   // 0..16383
    int q   = fl & 7;
    int row = (fl >> 3) & 63;
    int ck  = fl >> 9;
    int e = g_tile_e[tile];
    int m = g_tile_m0[tile] + row;
    __half2 h[4];
    if (m < g_counts[e]) {
        int tok = g_sorted[g_offsets[e] + m];
        int col = ck * BKH + q * 8;
        const float* src = (col < L_DIM) ? (x + (size_t)tok * L_DIM + col)
                                         : (y + (size_t)tok * L_DIM + (col - L_DIM));
        float4 v0 = *(const float4*)src;
        float4 v1 = *(const float4*)(src + 4);
        h[0] = __floats2half2_rn(v0.x, v0.y);
        h[1] = __floats2half2_rn(v0.z, v0.w);
        h[2] = __floats2half2_rn(v1.x, v1.y);
        h[3] = __floats2half2_rn(v1.z, v1.w);
    } else {
        h[0] = h[1] = h[2] = h[3] = __half2half2(__float2half(0.f));
    }
    __half* dst = inp_h + ((size_t)tile * A_TILE_HALVES + (size_t)ck * A_CHUNK_HALVES
                           + row * 64 + ((q ^ (row & 7)) << 3));
    *(uint4*)dst = *(uint4*)h;
}

// ---------------- grouped fp16 mma.sync GEMM, 256 threads, tile 64x128 ----------------
__global__ __launch_bounds__(256)
void moe_gemm_h(const float* __restrict__ be, float* __restrict__ out) {
    int tile = blockIdx.y;
    if (tile >= g_ntiles) return;
    int e = g_tile_e[tile];
    int m0 = g_tile_m0[tile];
    int cnt = g_counts[e];
    int nb = blockIdx.x;
    int n0 = nb * BN;
    const int* toks = g_sorted + g_offsets[e];

    const __half* asrc = inp_h + (size_t)tile * A_TILE_HALVES;
    const __half* bsrc = We_h + ((size_t)(e * 16 + nb) * 32) * B_CHUNK_HALVES;

    extern __shared__ char sm[];
    uint32_t sbase = smem_u32(sm);
    __shared__ __align__(8) uint64_t s_mbar[STAGES];
    uint32_t mb[STAGES];
#pragma unroll
    for (int s = 0; s < STAGES; s++) mb[s] = smem_u32(&s_mbar[s]);

    int tid = threadIdx.x, wid = tid >> 5, lane = tid & 31;
    int wm = wid & 1, wn = wid >> 1;          // 2x4 warp grid; warp tile 32(m) x 32(n)
    int lrow = lane >> 2, lc = lane & 3;
    int sw = lane & 7;
    uint32_t aRowBase = (uint32_t)(wm * 32 + ((lane >> 3) & 1) * 8 + sw);
    uint32_t kpa = (uint32_t)(lane >> 4);
    uint32_t nRowBase = (uint32_t)(wn * 32 + (lane >> 4) * 8 + sw);
    uint32_t kpb = (uint32_t)((lane >> 3) & 1);

    if (tid == 0) {
#pragma unroll
        for (int s = 0; s < STAGES; s++) MBAR_INIT(mb[s], 1);
    }
    __syncthreads();

    if (tid == 0) {
#pragma unroll
        for (int s = 0; s < STAGES - 1; s++) {
            uint32_t dst = sbase + s * STG_BYTES;
            MBAR_EXPECT_TX(mb[s], STG_BYTES);
            bulk_g2s(dst, asrc + (size_t)s * A_CHUNK_HALVES, A_BYTES, mb[s]);
            bulk_g2s(dst + A_BYTES, bsrc + (size_t)s * B_CHUNK_HALVES, B_BYTES, mb[s]);
        }
    }

    float acc[2][4][4];
#pragma unroll
    for (int i = 0; i < 2; i++)
#pragma unroll
        for (int j = 0; j < 4; j++)
#pragma unroll
            for (int q = 0; q < 4; q++) acc[i][j][q] = 0.f;

    for (int i = 0; i < NCH; i++) {
        int buf = i & (STAGES - 1);
        if (tid == 0 && i + STAGES - 1 < NCH) {
            int nxt = (i + STAGES - 1) & (STAGES - 1);
            uint32_t dst = sbase + nxt * STG_BYTES;
            MBAR_EXPECT_TX(mb[nxt], STG_BYTES);
            bulk_g2s(dst, asrc + (size_t)(i + STAGES - 1) * A_CHUNK_HALVES, A_BYTES, mb[nxt]);
            bulk_g2s(dst + A_BYTES, bsrc + (size_t)(i + STAGES - 1) * B_CHUNK_HALVES, B_BYTES, mb[nxt]);
        }
        MBAR_WAIT(mb[buf], (uint32_t)((i >> 2) & 1));

        uint32_t sA = sbase + buf * STG_BYTES;
        uint32_t sB = sA + A_BYTES;
#pragma unroll
        for (int ks = 0; ks < 4; ks++) {
            uint32_t a[2][4], b[2][4];
            uint32_t chA = (uint32_t)(((ks * 2 + kpa) ^ sw) << 4);
            uint32_t chB = (uint32_t)(((ks * 2 + kpb) ^ sw) << 4);
#pragma unroll
            for (int ii = 0; ii < 2; ii++)
                ldsm4(a[ii], sA + (aRowBase + ii * 16) * 128u + chA);
#pragma unroll
            for (int jp = 0; jp < 2; jp++)
                ldsm4(b[jp], sB + (nRowBase + jp * 16) * 128u + chB);
#pragma unroll
            for (int ii = 0; ii < 2; ii++)
#pragma unroll
                for (int jp = 0; jp < 2; jp++) {
                    mma_f16(acc[ii][jp * 2 + 0], a[ii], &b[jp][0]);
                    mma_f16(acc[ii][jp * 2 + 1], a[ii], &b[jp][2]);
                }
        }
        __syncthreads();
    }

    // ---- epilogue: bias + scatter to original token rows ----
    const float* brow_g = be + (size_t)e * D_DIM + n0 + wn * 32 + lc * 2;
    float2 bias[4];
#pragma unroll
    for (int j = 0; j < 4; j++) bias[j] = *(const float2*)(brow_g + j * 8);

#pragma unroll
    for (int ii = 0; ii < 2; ii++) {
#pragma unroll
        for (int h = 0; h < 2; h++) {
            int m = m0 + wm * 32 + ii * 16 + h * 8 + lrow;
            if (m < cnt) {
                int tok = toks[m];
                float* orow = out + (size_t)tok * D_DIM + n0 + wn * 32 + lc * 2;
#pragma unroll
                for (int j = 0; j < 4; j++) {
                    float2 v;
                    v.x = acc[ii][j][h * 2 + 0] + bias[j].x;
                    v.y = acc[ii][j][h * 2 + 1] + bias[j].y;
                    *(float2*)(orow + j * 8) = v;
                }
            }
        }
    }
}

extern "C" void kernel_launch(void* const* d_in, const int* in_sizes, int n_in,
                              void* d_out, int out_size) {
    const float* x  = (const float*)d_in[0];
    const float* y  = (const float*)d_in[1];
    const float* We = (const float*)d_in[2];
    const float* be = (const float*)d_in[3];
    const float* gW = (const float*)d_in[4];
    const float* gb = (const float*)d_in[5];
    float* out = (float*)d_out;

    static cudaStream_t s2 = nullptr;
    static cudaEvent_t evFork = nullptr, evWe = nullptr;
    if (!s2) {
        cudaFuncSetAttribute(moe_gemm_h, cudaFuncAttributeMaxDynamicSharedMemorySize, DYN_SMEM);
        cudaFuncSetAttribute(gate_kernel, cudaFuncAttributeMaxDynamicSharedMemorySize, GATE_SMEM);
        cudaStreamCreateWithFlags(&s2, cudaStreamNonBlocking);
        cudaEventCreateWithFlags(&evFork, cudaEventDisableTiming);
        cudaEventCreateWithFlags(&evWe, cudaEventDisableTiming);
    }

    // fork: conv_we runs on s2 concurrently with the gating chain
    cudaEventRecord(evFork, 0);
    cudaStreamWaitEvent(s2, evFork, 0);
    conv_we<<<(NE * D_DIM * D_DIM) / (256 * 8), 256, 0, s2>>>(We);
    cudaEventRecord(evWe, s2);

    gate_kernel<<<B_TOK / 32, 256, GATE_SMEM>>>(x, y, gW, gb);
    sortbuild_kernel<<<1, 1024>>>();
    conv_inp<<<MAX_TILES * 64, 256>>>(x, y);

    // join: GEMM needs We_h
    cudaStreamWaitEvent(0, evWe, 0);

    dim3 grid(D_DIM / BN, MAX_TILES, 1);   // 16 x 136; tiles >= g_ntiles exit early
    moe_gemm_h<<<grid, 256, DYN_SMEM>>>(be, out);
}

// round 11
// speedup vs baseline: 1.2013x; 1.0455x over previous
#include <cuda_runtime.h>
#include <cuda_fp16.h>
#include <cstdint>

#define B_TOK 8192
#define L_DIM 1024
#define D_DIM 2048
#define NE 8

#define BM 64
#define BN 128
#define BKH 64                        // fp16 k per chunk (128B rows)
#define NCH (D_DIM / BKH)             // 32
#define STAGES 3
#define A_BYTES (BM * 128)            // 8192
#define B_BYTES (BN * 128)            // 16384
#define STG_BYTES (A_BYTES + B_BYTES) // 24576
#define DYN_SMEM (STAGES * STG_BYTES) // 73728
#define GATE_SMEM (NE * D_DIM * 4)    // 65536

#define MAX_TILES 136
#define A_TILE_HALVES (BM * D_DIM)            // 131072 halves per tile
#define A_CHUNK_HALVES (BM * BKH)             // 4096 halves = 8KB
#define B_CHUNK_HALVES (BN * BKH)             // 8192 halves = 16KB

// ---------------- scratch (allocation-free rule: __device__ globals) ----------------
__device__ int g_expert[B_TOK];
__device__ int g_counts[NE];
__device__ int g_offsets[NE + 1];
__device__ int g_sorted[B_TOK];
__device__ int g_tilebase[NE];
__device__ int g_tile_e[MAX_TILES];
__device__ int g_tile_m0[MAX_TILES];
__device__ int g_ntiles;
__device__ __half We_h[(size_t)NE * D_DIM * D_DIM];        // 64 MB, chunk-major swizzled
__device__ __half inp_h[(size_t)MAX_TILES * A_TILE_HALVES]; // ~35.7 MB, tile/chunk-major swizzled

// ---------------- helpers ----------------
__device__ __forceinline__ uint32_t smem_u32(const void* p) {
    uint32_t a;
    asm("{ .reg .u64 t; cvta.to.shared.u64 t, %1; cvt.u32.u64 %0, t; }" : "=r"(a) : "l"(p));
    return a;
}
__device__ __forceinline__ void ldsm4(uint32_t* r, uint32_t addr) {
    asm volatile("ldmatrix.sync.aligned.m8n8.x4.shared.b16 {%0,%1,%2,%3}, [%4];"
                 : "=r"(r[0]), "=r"(r[1]), "=r"(r[2]), "=r"(r[3]) : "r"(addr));
}
__device__ __forceinline__ void mma_f16(float* d, const uint32_t* a, const uint32_t* b) {
    asm volatile("mma.sync.aligned.m16n8k16.row.col.f32.f16.f16.f32 "
                 "{%0,%1,%2,%3}, {%4,%5,%6,%7}, {%8,%9}, {%0,%1,%2,%3};"
                 : "+f"(d[0]), "+f"(d[1]), "+f"(d[2]), "+f"(d[3])
                 : "r"(a[0]), "r"(a[1]), "r"(a[2]), "r"(a[3]), "r"(b[0]), "r"(b[1]));
}
#define MBAR_INIT(addr, count) \
    asm volatile("mbarrier.init.shared.b64 [%0], %1;" :: "r"(addr), "r"((uint32_t)(count)) : "memory")
#define MBAR_EXPECT_TX(addr, bytes) \
    asm volatile("mbarrier.arrive.expect_tx.shared.b64 _, [%0], %1;" :: "r"(addr), "r"((uint32_t)(bytes)) : "memory")
#define MBAR_WAIT(addr, parity) do {                                                \
    uint32_t _m = (addr); uint32_t _p = (parity); uint32_t _done;                   \
    asm volatile("{\n\t.reg .pred p;\n\t"                                           \
        "mbarrier.try_wait.parity.acquire.cta.shared::cta.b64 p, [%1], %2;\n\t"     \
        "selp.b32 %0, 1, 0, p;\n\t}" : "=r"(_done) : "r"(_m), "r"(_p) : "memory");  \
    if (!_done) {                                                                   \
        asm volatile("{\n\t.reg .pred P1;\n\t"                                      \
            "WL_%=:\n\t"                                                            \
            "mbarrier.try_wait.parity.acquire.cta.shared::cta.b64 P1, [%0], %1, 0x989680;\n\t" \
            "@P1 bra.uni WD_%=;\n\t"                                                \
            "bra.uni WL_%=;\n\t"                                                    \
            "WD_%=:\n\t}" :: "r"(_m), "r"(_p) : "memory");                          \
    }                                                                               \
} while (0)
__device__ __forceinline__ void bulk_g2s(uint32_t dst, const void* src, uint32_t bytes, uint32_t mbar) {
    asm volatile("cp.async.bulk.shared::cluster.global.mbarrier::complete_tx::bytes [%0], [%1], %2, [%3];"
                 :: "r"(dst), "l"(src), "r"(bytes), "r"(mbar) : "memory");
}

// ---------------- gating ----------------
__global__ void gate_kernel(const float* __restrict__ x, const float* __restrict__ y,
                            const float* __restrict__ gW, const float* __restrict__ gb) {
    extern __shared__ float sgW[];
    int tid = threadIdx.x;
    for (int i = tid; i < NE * D_DIM / 4; i += 256)
        ((float4*)sgW)[i] = ((const float4*)gW)[i];
    __syncthreads();

    int wid = tid >> 5, lane = tid & 31;
#pragma unroll
    for (int t = 0; t < 4; t++) {
        int tok = blockIdx.x * 32 + wid * 4 + t;
        const float4* xr = (const float4*)(x + (size_t)tok * L_DIM);
        const float4* yr = (const float4*)(y + (size_t)tok * L_DIM);
        float acc[NE];
#pragma unroll
        for (int e = 0; e < NE; e++) acc[e] = 0.f;
#pragma unroll
        for (int it = 0; it < 8; it++) {
            float4 v = xr[it * 32 + lane];
            int kb = (it * 32 + lane) * 4;
#pragma unroll
            for (int e = 0; e < NE; e++) {
                float4 w = *(const float4*)(sgW + e * D_DIM + kb);
                acc[e] += v.x * w.x + v.y * w.y + v.z * w.z + v.w * w.w;
            }
        }
#pragma unroll
        for (int it = 0; it < 8; it++) {
            float4 v = yr[it * 32 + lane];
            int kb = L_DIM + (it * 32 + lane) * 4;
#pragma unroll
            for (int e = 0; e < NE; e++) {
                float4 w = *(const float4*)(sgW + e * D_DIM + kb);
                acc[e] += v.x * w.x + v.y * w.y + v.z * w.z + v.w * w.w;
            }
        }
#pragma unroll
        for (int e = 0; e < NE; e++) {
#pragma unroll
            for (int off = 16; off > 0; off >>= 1)
                acc[e] += __shfl_xor_sync(0xffffffffu, acc[e], off);
        }
        if (lane == 0) {
            int best = 0;
            float bv = acc[0] + gb[0];
#pragma unroll
            for (int e = 1; e < NE; e++) {
                float v = acc[e] + gb[e];
                if (v > bv) { bv = v; best = e; }
            }
            g_expert[tok] = best;
        }
    }
}

// ---------------- fused count + scan + tile-table + rank-scatter (1 block) ----------------
__global__ void sortbuild_kernel() {
    __shared__ int s_cnt[NE];
    __shared__ int s_off[NE];
    int tid = threadIdx.x;            // 1024 threads
    int lane = tid & 31;
    if (tid < NE) s_cnt[tid] = 0;
    __syncthreads();

    int ex[8];
#pragma unroll
    for (int i = 0; i < 8; i++) ex[i] = g_expert[i * 1024 + tid];

    int lc[NE];
#pragma unroll
    for (int e = 0; e < NE; e++) lc[e] = 0;
#pragma unroll
    for (int i = 0; i < 8; i++)
#pragma unroll
        for (int e = 0; e < NE; e++) lc[e] += (ex[i] == e) ? 1 : 0;
#pragma unroll
    for (int e = 0; e < NE; e++) {
#pragma unroll
        for (int off = 16; off > 0; off >>= 1)
            lc[e] += __shfl_xor_sync(0xffffffffu, lc[e], off);
    }
    if (lane == 0) {
#pragma unroll
        for (int e = 0; e < NE; e++) atomicAdd(&s_cnt[e], lc[e]);
    }
    __syncthreads();

    if (tid == 0) {
        int s = 0, tile = 0;
#pragma unroll
        for (int e = 0; e < NE; e++) {
            int c = s_cnt[e];
            g_counts[e] = c;
            g_offsets[e] = s;
            s_off[e] = s;
            g_tilebase[e] = tile;
            int nt = (c + BM - 1) / BM;
            for (int t = 0; t < nt; t++) {
                g_tile_e[tile] = e;
                g_tile_m0[tile] = t * BM;
                tile++;
            }
            s += c;
        }
        g_offsets[NE] = s;
        g_ntiles = tile;
    }
    __syncthreads();

#pragma unroll
    for (int i = 0; i < 8; i++) {
        int tok = i * 1024 + tid;
        int e = ex[i];
        unsigned peers = __match_any_sync(0xffffffffu, e);
        int leader = __ffs(peers) - 1;
        int lrank = __popc(peers & ((1u << lane) - 1u));
        int base = 0;
        if (lane == leader) base = atomicAdd(&s_off[e], __popc(peers));
        base = __shfl_sync(0xffffffffu, base, leader);
        g_sorted[base + lrank] = tok;
    }
}

// ---------------- conversion to chunk-major swizzled fp16 (2 items/thread for MLP) ----------------
// We_h layout: [e][nb(16)][ck(32)][row(128)][64 halves], 16B chunk q stored at (q ^ (row&7)).
#define WE_UNITS (NE * D_DIM * D_DIM / 8)      // 4194304 uint4-units
__global__ void conv_we(const float* __restrict__ We) {
    uint32_t u0 = blockIdx.x * 256 + threadIdx.x;
    uint32_t u1 = u0 + WE_UNITS / 2;
    const float* src[2];
    __half* dst[2];
#pragma unroll
    for (int k = 0; k < 2; k++) {
        uint32_t flat = k ? u1 : u0;
        int q   = flat & 7;
        int row = (flat >> 3) & 127;
        int ck  = (flat >> 10) & 31;
        int nb  = (flat >> 15) & 15;
        int e   = flat >> 19;
        src[k] = We + ((((size_t)e * D_DIM) + nb * 128 + row) * D_DIM + ck * BKH + q * 8);
        dst[k] = We_h + (((size_t)(e * 16 + nb) * 32 + ck) * B_CHUNK_HALVES
                         + row * 64 + ((q ^ (row & 7)) << 3));
    }
    float4 a0 = *(const float4*)src[0];
    float4 a1 = *(const float4*)(src[0] + 4);
    float4 b0 = *(const float4*)src[1];
    float4 b1 = *(const float4*)(src[1] + 4);
    __half2 ha[4], hb[4];
    ha[0] = __floats2half2_rn(a0.x, a0.y); ha[1] = __floats2half2_rn(a0.z, a0.w);
    ha[2] = __floats2half2_rn(a1.x, a1.y); ha[3] = __floats2half2_rn(a1.z, a1.w);
    hb[0] = __floats2half2_rn(b0.x, b0.y); hb[1] = __floats2half2_rn(b0.z, b0.w);
    hb[2] = __floats2half2_rn(b1.x, b1.y); hb[3] = __floats2half2_rn(b1.z, b1.w);
    *(uint4*)dst[0] = *(uint4*)ha;
    *(uint4*)dst[1] = *(uint4*)hb;
}

// inp_h layout: [tile][ck(32)][row(64)][64 halves], swizzled; rows = sorted tokens.
__global__ void conv_inp(const float* __restrict__ x, const float* __restrict__ y) {
    int tile = blockIdx.x >> 5;
    if (tile >= g_ntiles) return;
    int e = g_tile_e[tile];
    int cnt = g_counts[e];
    int moff = g_tile_m0[tile];
    const int* toks = g_sorted + g_offsets[e];
    uint32_t base_fl = (blockIdx.x & 31) * 256 + threadIdx.x;   // 0..8191
#pragma unroll
    for (int k = 0; k < 2; k++) {
        uint32_t fl = base_fl + k * 8192;
        int q   = fl & 7;
        int row = (fl >> 3) & 63;
        int ck  = fl >> 9;
        int m = moff + row;
        __half2 h[4];
        if (m < cnt) {
            int tok = toks[m];
            int col = ck * BKH + q * 8;
            const float* src = (col < L_DIM) ? (x + (size_t)tok * L_DIM + col)
                                             : (y + (size_t)tok * L_DIM + (col - L_DIM));
            float4 v0 = *(const float4*)src;
            float4 v1 = *(const float4*)(src + 4);
            h[0] = __floats2half2_rn(v0.x, v0.y);
            h[1] = __floats2half2_rn(v0.z, v0.w);
            h[2] = __floats2half2_rn(v1.x, v1.y);
            h[3] = __floats2half2_rn(v1.z, v1.w);
        } else {
            h[0] = h[1] = h[2] = h[3] = __half2half2(__float2half(0.f));
        }
        __half* dst = inp_h + ((size_t)tile * A_TILE_HALVES + (size_t)ck * A_CHUNK_HALVES
                               + row * 64 + ((q ^ (row & 7)) << 3));
        *(uint4*)dst = *(uint4*)h;
    }
}

// ---------------- grouped fp16 mma.sync GEMM, 256 threads, tile 64x128, 3 CTAs/SM ----------------
__global__ __launch_bounds__(256, 3)
void moe_gemm_h(const float* __restrict__ be, float* __restrict__ out) {
    int tile = blockIdx.y;
    if (tile >= g_ntiles) return;
    int e = g_tile_e[tile];
    int m0 = g_tile_m0[tile];
    int cnt = g_counts[e];
    int nb = blockIdx.x;
    int n0 = nb * BN;
    const int* toks = g_sorted + g_offsets[e];

    const __half* asrc = inp_h + (size_t)tile * A_TILE_HALVES;
    const __half* bsrc = We_h + ((size_t)(e * 16 + nb) * 32) * B_CHUNK_HALVES;

    extern __shared__ char sm[];
    uint32_t sbase = smem_u32(sm);
    __shared__ __align__(8) uint64_t s_mbar[STAGES];
    uint32_t mb[STAGES];
#pragma unroll
    for (int s = 0; s < STAGES; s++) mb[s] = smem_u32(&s_mbar[s]);

    int tid = threadIdx.x, wid = tid >> 5, lane = tid & 31;
    int wm = wid & 1, wn = wid >> 1;          // 2x4 warp grid; warp tile 32(m) x 32(n)
    int lrow = lane >> 2, lc = lane & 3;
    int sw = lane & 7;
    uint32_t aRowBase = (uint32_t)(wm * 32 + ((lane >> 3) & 1) * 8 + sw);
    uint32_t kpa = (uint32_t)(lane >> 4);
    uint32_t nRowBase = (uint32_t)(wn * 32 + (lane >> 4) * 8 + sw);
    uint32_t kpb = (uint32_t)((lane >> 3) & 1);

    if (tid == 0) {
#pragma unroll
        for (int s = 0; s < STAGES; s++) MBAR_INIT(mb[s], 1);
    }
    __syncthreads();

    if (tid == 0) {
#pragma unroll
        for (int s = 0; s < STAGES - 1; s++) {
            uint32_t dst = sbase + s * STG_BYTES;
            MBAR_EXPECT_TX(mb[s], STG_BYTES);
            bulk_g2s(dst, asrc + (size_t)s * A_CHUNK_HALVES, A_BYTES, mb[s]);
            bulk_g2s(dst + A_BYTES, bsrc + (size_t)s * B_CHUNK_HALVES, B_BYTES, mb[s]);
        }
    }

    float acc[2][4][4];
#pragma unroll
    for (int i = 0; i < 2; i++)
#pragma unroll
        for (int j = 0; j < 4; j++)
#pragma unroll
            for (int q = 0; q < 4; q++) acc[i][j][q] = 0.f;

    int buf = 0, nxt = STAGES - 1, par = 0;
    for (int i = 0; i < NCH; i++) {
        if (tid == 0 && i + STAGES - 1 < NCH) {
            uint32_t dst = sbase + nxt * STG_BYTES;
            MBAR_EXPECT_TX(mb[nxt], STG_BYTES);
            bulk_g2s(dst, asrc + (size_t)(i + STAGES - 1) * A_CHUNK_HALVES, A_BYTES, mb[nxt]);
            bulk_g2s(dst + A_BYTES, bsrc + (size_t)(i + STAGES - 1) * B_CHUNK_HALVES, B_BYTES, mb[nxt]);
        }
        MBAR_WAIT(mb[buf], (uint32_t)par);

        uint32_t sA = sbase + buf * STG_BYTES;
        uint32_t sB = sA + A_BYTES;
#pragma unroll
        for (int ks = 0; ks < 4; ks++) {
            uint32_t a[2][4], b[2][4];
            uint32_t chA = (uint32_t)(((ks * 2 + kpa) ^ sw) << 4);
            uint32_t chB = (uint32_t)(((ks * 2 + kpb) ^ sw) << 4);
#pragma unroll
            for (int ii = 0; ii < 2; ii++)
                ldsm4(a[ii], sA + (aRowBase + ii * 16) * 128u + chA);
#pragma unroll
            for (int jp = 0; jp < 2; jp++)
                ldsm4(b[jp], sB + (nRowBase + jp * 16) * 128u + chB);
#pragma unroll
            for (int ii = 0; ii < 2; ii++)
#pragma unroll
                for (int jp = 0; jp < 2; jp++) {
                    mma_f16(acc[ii][jp * 2 + 0], a[ii], &b[jp][0]);
                    mma_f16(acc[ii][jp * 2 + 1], a[ii], &b[jp][2]);
                }
        }
        __syncthreads();
        buf++; nxt++;
        if (buf == STAGES) { buf = 0; par ^= 1; }
        if (nxt == STAGES) nxt = 0;
    }

    // ---- epilogue: bias + scatter to original token rows ----
    const float* brow_g = be + (size_t)e * D_DIM + n0 + wn * 32 + lc * 2;
    float2 bias[4];
#pragma unroll
    for (int j = 0; j < 4; j++) bias[j] = *(const float2*)(brow_g + j * 8);

#pragma unroll
    for (int ii = 0; ii < 2; ii++) {
#pragma unroll
        for (int h = 0; h < 2; h++) {
            int m = m0 + wm * 32 + ii * 16 + h * 8 + lrow;
            if (m < cnt) {
                int tok = toks[m];
                float* orow = out + (size_t)tok * D_DIM + n0 + wn * 32 + lc * 2;
#pragma unroll
                for (int j = 0; j < 4; j++) {
                    float2 v;
                    v.x = acc[ii][j][h * 2 + 0] + bias[j].x;
                    v.y = acc[ii][j][h * 2 + 1] + bias[j].y;
                    *(float2*)(orow + j * 8) = v;
                }
            }
        }
    }
}

extern "C" void kernel_launch(void* const* d_in, const int* in_sizes, int n_in,
                              void* d_out, int out_size) {
    const float* x  = (const float*)d_in[0];
    const float* y  = (const float*)d_in[1];
    const float* We = (const float*)d_in[2];
    const float* be = (const float*)d_in[3];
    const float* gW = (const float*)d_in[4];
    const float* gb = (const float*)d_in[5];
    float* out = (float*)d_out;

    static cudaStream_t s2 = nullptr;
    static cudaEvent_t evFork = nullptr, evWe = nullptr;
    if (!s2) {
        cudaFuncSetAttribute(moe_gemm_h, cudaFuncAttributeMaxDynamicSharedMemorySize, DYN_SMEM);
        cudaFuncSetAttribute(gate_kernel, cudaFuncAttributeMaxDynamicSharedMemorySize, GATE_SMEM);
        cudaStreamCreateWithFlags(&s2, cudaStreamNonBlocking);
        cudaEventCreateWithFlags(&evFork, cudaEventDisableTiming);
        cudaEventCreateWithFlags(&evWe, cudaEventDisableTiming);
    }

    // fork: conv_we runs on s2 concurrently with the gating chain
    cudaEventRecord(evFork, 0);
    cudaStreamWaitEvent(s2, evFork, 0);
    conv_we<<<WE_UNITS / 2 / 256, 256, 0, s2>>>(We);
    cudaEventRecord(evWe, s2);

    gate_kernel<<<B_TOK / 32, 256, GATE_SMEM>>>(x, y, gW, gb);
    sortbuild_kernel<<<1, 1024>>>();
    conv_inp<<<MAX_TILES * 32, 256>>>(x, y);

    // join: GEMM needs We_h
    cudaStreamWaitEvent(0, evWe, 0);

    dim3 grid(D_DIM / BN, MAX_TILES, 1);   // 16 x 136; tiles >= g_ntiles exit early
    moe_gemm_h<<<grid, 256, DYN_SMEM>>>(be, out);
}